// round 6
// baseline (speedup 1.0000x reference)
#include <cuda_runtime.h>
#include <stdint.h>

#define NSTEPS 2176
#define BURN   128
#define DD     512
#define HH     1024

// Scratch (static device globals — no allocation anywhere)
__device__ float g_sn[NSTEPS * DD];   // 0.1 * normal noise rows
__device__ float g_N [NSTEPS * HH];   // (0.1*noise_t) @ W1
__device__ float g_u [NSTEPS];        // uniform accept draws
__device__ uint2 g_knoise[NSTEPS];    // per-step noise subkeys

// ---------------- threefry2x32 (exact JAX) ----------------
__device__ __forceinline__ uint32_t rotl32(uint32_t v, int r) {
    return (v << r) | (v >> (32 - r));
}

__device__ __forceinline__ void threefry(uint32_t k0, uint32_t k1,
                                         uint32_t x0, uint32_t x1,
                                         uint32_t& o0, uint32_t& o1) {
    uint32_t ks2 = k0 ^ k1 ^ 0x1BD11BDAu;
    x0 += k0; x1 += k1;
#define TF_R(r) { x0 += x1; x1 = rotl32(x1, (r)); x1 ^= x0; }
    TF_R(13) TF_R(15) TF_R(26) TF_R(6)
    x0 += k1;  x1 += ks2 + 1u;
    TF_R(17) TF_R(29) TF_R(16) TF_R(24)
    x0 += ks2; x1 += k0 + 2u;
    TF_R(13) TF_R(15) TF_R(26) TF_R(6)
    x0 += k0;  x1 += k1 + 3u;
    TF_R(17) TF_R(29) TF_R(16) TF_R(24)
    x0 += k1;  x1 += ks2 + 4u;
    TF_R(13) TF_R(15) TF_R(26) TF_R(6)
    x0 += ks2; x1 += k0 + 5u;
#undef TF_R
    o0 = x0; o1 = x1;
}

// ---------------- XLA-matching math ----------------
__device__ __forceinline__ float erfinv_xla(float x) {
    float w = -log1pf(-x * x);
    float p;
    if (w < 5.0f) {
        w = w - 2.5f;
        p = 2.81022636e-08f;
        p = fmaf(p, w, 3.43273939e-07f);
        p = fmaf(p, w, -3.5233877e-06f);
        p = fmaf(p, w, -4.39150654e-06f);
        p = fmaf(p, w, 0.00021858087f);
        p = fmaf(p, w, -0.00125372503f);
        p = fmaf(p, w, -0.00417768164f);
        p = fmaf(p, w, 0.246640727f);
        p = fmaf(p, w, 1.50140941f);
    } else {
        w = sqrtf(w) - 3.0f;
        p = -0.000200214257f;
        p = fmaf(p, w, 0.000100950558f);
        p = fmaf(p, w, 0.00134934322f);
        p = fmaf(p, w, -0.00367342844f);
        p = fmaf(p, w, 0.00573950773f);
        p = fmaf(p, w, -0.0076224613f);
        p = fmaf(p, w, 0.00943887047f);
        p = fmaf(p, w, 1.00167406f);
        p = fmaf(p, w, 2.83297682f);
    }
    return p * x;
}

__device__ __forceinline__ float tanh_xla(float x) {
    const float kMax = 7.90531110763549805f;
    float xc = fminf(fmaxf(x, -kMax), kMax);
    float x2 = xc * xc;
    float np_ = fmaf(x2, -2.76076847742355e-16f, 2.00018790482477e-13f);
    np_ = fmaf(x2, np_, -8.60467152213735e-11f);
    np_ = fmaf(x2, np_, 5.12229709037114e-08f);
    np_ = fmaf(x2, np_, 1.48572235717979e-05f);
    np_ = fmaf(x2, np_, 6.37261928875436e-04f);
    np_ = fmaf(x2, np_, 4.89352455891786e-03f);
    np_ = xc * np_;
    float dp = fmaf(x2, 1.19825839466702e-06f, 1.18534705686654e-04f);
    dp = fmaf(x2, dp, 2.26843463243900e-03f);
    dp = fmaf(x2, dp, 4.89352518554385e-03f);
    float r = np_ / dp;
    return (fabsf(x) < 0.0004f) ? x : r;
}

__device__ __forceinline__ float bits_to_u01(uint32_t bits) {
    return __uint_as_float((bits >> 9) | 0x3F800000u) - 1.0f;
}

__device__ __forceinline__ float bits_to_scaled_normal(uint32_t bits) {
    const float lo = -0.99999994039535522461f;
    float f = bits_to_u01(bits);
    float v = fmaxf(lo, fmaf(f, 2.0f, lo));
    float n = 1.41421353816986083984f * erfinv_xla(v);
    return 0.1f * n;
}

// ---------------- Phase 0: step keys + uniforms (partitionable threefry) ----------------
__global__ void keygen_kernel() {
    int t = blockIdx.x * blockDim.x + threadIdx.x;
    if (t >= NSTEPS) return;
    uint32_t a, b;
    threefry(0u, 1u, 0u, (uint32_t)t, a, b);
    uint32_t n0, n1, u0, u1;
    threefry(a, b, 0u, 0u, n0, n1);
    threefry(a, b, 0u, 1u, u0, u1);
    g_knoise[t] = make_uint2(n0, n1);
    uint32_t c, d;
    threefry(u0, u1, 0u, 0u, c, d);
    g_u[t] = bits_to_u01(c ^ d);
}

// ---------------- Phase 1: scaled normals ----------------
__global__ void noise_kernel() {
    int t = blockIdx.x;
    int i = threadIdx.x;
    uint2 k = g_knoise[t];
    uint32_t r0, r1;
    threefry(k.x, k.y, 0u, (uint32_t)i, r0, r1);
    g_sn[t * DD + i] = bits_to_scaled_normal(r0 ^ r1);
}

// ---------------- Phase 2: N = sn @ W1  (fp32 FFMA GEMM, DRAM-bound, ~3us) ----------------
#define BM 64
#define BN 64
#define BK 16
__global__ __launch_bounds__(256) void gemm_kernel(const float* __restrict__ W1) {
    __shared__ float As[BK][BM];
    __shared__ float Bs[BK][BN];
    int m0 = blockIdx.y * BM;
    int n0 = blockIdx.x * BN;
    int tid = threadIdx.x;
    int tx = tid % 16, ty = tid / 16;
    float acc[4][4] = {};
    for (int k0 = 0; k0 < DD; k0 += BK) {
#pragma unroll
        for (int l = tid; l < BM * BK; l += 256) {
            int m = l / BK, k = l % BK;
            As[k][m] = g_sn[(m0 + m) * DD + k0 + k];
        }
#pragma unroll
        for (int l = tid; l < BK * BN; l += 256) {
            int k = l / BN, n = l % BN;
            Bs[k][n] = W1[(k0 + k) * HH + n0 + n];
        }
        __syncthreads();
#pragma unroll
        for (int kk = 0; kk < BK; kk++) {
            float a[4], b[4];
#pragma unroll
            for (int i = 0; i < 4; i++) a[i] = As[kk][ty * 4 + i];
#pragma unroll
            for (int j = 0; j < 4; j++) b[j] = Bs[kk][tx * 4 + j];
#pragma unroll
            for (int i = 0; i < 4; i++)
#pragma unroll
                for (int j = 0; j < 4; j++)
                    acc[i][j] = fmaf(a[i], b[j], acc[i][j]);
        }
        __syncthreads();
    }
#pragma unroll
    for (int i = 0; i < 4; i++)
#pragma unroll
        for (int j = 0; j < 4; j++)
            g_N[(m0 + ty * 4 + i) * HH + n0 + tx * 4 + j] = acc[i][j];
}

// ---------------- Phase 3: sequential MH chain, one-step branch speculation ----------------
// 256 threads, 4 hidden units/thread. Iteration t: scalar chain decides step t
// (using sums speculated last iteration) WHILE the vector pipeline computes both
// candidate sums for step t+1 (accept/reject branches of step t) — independent of
// the pending decision. One barrier/step, double-buffered partials.
// Arithmetic is bitwise identical to the sequential version.
__global__ __launch_bounds__(256, 1) void chain_kernel(
    const float* __restrict__ x0, const float* __restrict__ W1,
    const float* __restrict__ b1, const float* __restrict__ W2,
    const float* __restrict__ b2, float* __restrict__ out) {
    int tid  = threadIdx.x;
    int lane = tid & 31;
    int w    = tid >> 5;

    __shared__ __align__(16) float s_part[2][16];  // [buf][0..7 = A partials, 8..15 = B]
    __shared__ float s_x0[DD];
    __shared__ float s_u[NSTEPS];

    for (int i = tid; i < NSTEPS; i += 256) s_u[i] = g_u[i];
    {
        float2 t2 = ((const float2*)x0)[tid];
        s_x0[2 * tid] = t2.x; s_x0[2 * tid + 1] = t2.y;
    }
    __syncthreads();

    // z_j = b1_j + x0 @ W1[:, j]
    float z[4];
    {
        float4 bv = ((const float4*)b1)[tid];
        z[0] = bv.x; z[1] = bv.y; z[2] = bv.z; z[3] = bv.w;
    }
    const float4* W1v = (const float4*)W1;
#pragma unroll 4
    for (int d = 0; d < DD; d++) {
        float xv = s_x0[d];
        float4 wv = W1v[d * (HH / 4) + tid];
        z[0] = fmaf(xv, wv.x, z[0]);
        z[1] = fmaf(xv, wv.y, z[1]);
        z[2] = fmaf(xv, wv.z, z[2]);
        z[3] = fmaf(xv, wv.w, z[3]);
    }

    float4 w2v = ((const float4*)W2)[tid];
    float b2v = b2[0];
    float2 x = ((const float2*)x0)[tid];

    const float4* Nv  = (const float4*)g_N;   // row stride HH/4 = 256
    const float2* snv = (const float2*)g_sn;  // row stride DD/2 = 256

    // p_old = psi2(x0)  (buffer 0)
    float p_old;
    {
        float h, p;
        h = tanh_xla(z[0]); p = h * w2v.x;
        h = tanh_xla(z[1]); p = fmaf(h, w2v.y, p);
        h = tanh_xla(z[2]); p = fmaf(h, w2v.z, p);
        h = tanh_xla(z[3]); p = fmaf(h, w2v.w, p);
#pragma unroll
        for (int o = 16; o; o >>= 1) p += __shfl_xor_sync(0xFFFFFFFFu, p, o);
        if (lane == 0) s_part[0][w] = p;
        __syncthreads();
        float4 pa = *(const float4*)&s_part[0][0];
        float4 pb = *(const float4*)&s_part[0][4];
        float v = ((pa.x + pa.y) + (pa.z + pa.w)) + ((pb.x + pb.y) + (pb.z + pb.w));
        float o_ = v + b2v;
        p_old = o_ * o_;
    }

    // S_0 = sum for step 0 (single branch; buffer 1)
    float Ncur_x, Ncur_y, Ncur_z, Ncur_w;
    { float4 t4 = Nv[tid]; Ncur_x = t4.x; Ncur_y = t4.y; Ncur_z = t4.z; Ncur_w = t4.w; }
    float SA, SB;
    {
        float h, p;
        h = tanh_xla(z[0] + Ncur_x); p = h * w2v.x;
        h = tanh_xla(z[1] + Ncur_y); p = fmaf(h, w2v.y, p);
        h = tanh_xla(z[2] + Ncur_z); p = fmaf(h, w2v.z, p);
        h = tanh_xla(z[3] + Ncur_w); p = fmaf(h, w2v.w, p);
#pragma unroll
        for (int o = 16; o; o >>= 1) p += __shfl_xor_sync(0xFFFFFFFFu, p, o);
        if (lane == 0) s_part[1][w] = p;
        __syncthreads();
        float4 pa = *(const float4*)&s_part[1][0];
        float4 pb = *(const float4*)&s_part[1][4];
        SA = ((pa.x + pa.y) + (pa.z + pa.w)) + ((pb.x + pb.y) + (pb.z + pb.w));
        SB = SA;
    }
    bool accPrev = false;

    // row prefetch: Ncur = row t, Nnext = row t+1, Nn2 = row t+2
    float4 Nnext = Nv[256 + tid];
    float4 Nn2   = Nv[2 * 256 + tid];
    float2 sc    = snv[tid];
    float2 snn   = snv[256 + tid];
    float  uc    = s_u[0];
    float  un    = s_u[1];

    for (int t = 0; t < NSTEPS; t++) {
        // ---- scalar decision chain for step t (uses SA/SB from last iteration) ----
        float S     = accPrev ? SB : SA;
        float o_    = S + b2v;
        float p_new = o_ * o_;
        float ratio = fminf(p_new / (p_old + 1e-12f), 1.0f);
        bool  acc   = (uc < ratio);

        // ---- vector: speculative sums for step t+1 (independent of acc) ----
        float zB0 = z[0] + Ncur_x;               // accept-branch z candidate (== old 'pre')
        float zB1 = z[1] + Ncur_y;
        float zB2 = z[2] + Ncur_z;
        float zB3 = z[3] + Ncur_w;
        float hA, hB, pA, pB;
        hA = tanh_xla(z[0] + Nnext.x); pA = hA * w2v.x;
        hB = tanh_xla(zB0  + Nnext.x); pB = hB * w2v.x;
        hA = tanh_xla(z[1] + Nnext.y); pA = fmaf(hA, w2v.y, pA);
        hB = tanh_xla(zB1  + Nnext.y); pB = fmaf(hB, w2v.y, pB);
        hA = tanh_xla(z[2] + Nnext.z); pA = fmaf(hA, w2v.z, pA);
        hB = tanh_xla(zB2  + Nnext.z); pB = fmaf(hB, w2v.z, pB);
        hA = tanh_xla(z[3] + Nnext.w); pA = fmaf(hA, w2v.w, pA);
        hB = tanh_xla(zB3  + Nnext.w); pB = fmaf(hB, w2v.w, pB);
#pragma unroll
        for (int o = 16; o; o >>= 1) {
            pA += __shfl_xor_sync(0xFFFFFFFFu, pA, o);
            pB += __shfl_xor_sync(0xFFFFFFFFu, pB, o);
        }
        int buf = t & 1;
        if (lane == 0) s_part[buf][w] = pA;
        if (lane == 1) s_part[buf][8 + w] = pB;
        __syncthreads();                          // the only barrier per step

        // sums for step t+1
        {
            float4 qa0 = *(const float4*)&s_part[buf][0];
            float4 qa1 = *(const float4*)&s_part[buf][4];
            float4 qb0 = *(const float4*)&s_part[buf][8];
            float4 qb1 = *(const float4*)&s_part[buf][12];
            SA = ((qa0.x + qa0.y) + (qa0.z + qa0.w)) + ((qa1.x + qa1.y) + (qa1.z + qa1.w));
            SB = ((qb0.x + qb0.y) + (qb0.z + qb0.w)) + ((qb1.x + qb1.y) + (qb1.z + qb1.w));
        }

        // ---- resolve state for step t ----
        if (acc) {
            p_old = p_new;
            z[0] = zB0; z[1] = zB1; z[2] = zB2; z[3] = zB3;
            x.x += sc.x; x.y += sc.y;
        }
        accPrev = acc;
        if (t >= BURN) ((float2*)out)[(t - BURN) * (DD / 2) + tid] = x;

        // rotate / prefetch (guarded; stale values only feed discarded work)
        Ncur_x = Nnext.x; Ncur_y = Nnext.y; Ncur_z = Nnext.z; Ncur_w = Nnext.w;
        Nnext = Nn2;
        sc = snn;
        uc = un;
        if (t + 3 < NSTEPS) Nn2 = Nv[(t + 3) * 256 + tid];
        if (t + 2 < NSTEPS) {
            snn = snv[(t + 2) * 256 + tid];
            un  = s_u[t + 2];
        }
    }
}

// ---------------- launch ----------------
extern "C" void kernel_launch(void* const* d_in, const int* in_sizes, int n_in,
                              void* d_out, int out_size) {
    const float* x0 = (const float*)d_in[0];
    const float* W1 = (const float*)d_in[1];
    const float* b1 = (const float*)d_in[2];
    const float* W2 = (const float*)d_in[3];
    const float* b2 = (const float*)d_in[4];
    float* out = (float*)d_out;

    keygen_kernel<<<(NSTEPS + 255) / 256, 256>>>();
    noise_kernel<<<NSTEPS, 512>>>();
    gemm_kernel<<<dim3(HH / BN, NSTEPS / BM), 256>>>(W1);
    chain_kernel<<<1, 256>>>(x0, W1, b1, W2, b2, out);
}

// round 7
// speedup vs baseline: 1.1721x; 1.1721x over previous
#include <cuda_runtime.h>
#include <stdint.h>

#define NSTEPS 2176
#define BURN   128
#define DD     512
#define HH     1024

// Scratch (static device globals — no allocation anywhere)
__device__ float g_sn[NSTEPS * DD];   // 0.1 * normal noise rows
__device__ float g_N [NSTEPS * HH];   // (0.1*noise_t) @ W1
__device__ float g_u [NSTEPS];        // uniform accept draws
__device__ uint2 g_knoise[NSTEPS];    // per-step noise subkeys

// ---------------- threefry2x32 (exact JAX) ----------------
__device__ __forceinline__ uint32_t rotl32(uint32_t v, int r) {
    return (v << r) | (v >> (32 - r));
}

__device__ __forceinline__ void threefry(uint32_t k0, uint32_t k1,
                                         uint32_t x0, uint32_t x1,
                                         uint32_t& o0, uint32_t& o1) {
    uint32_t ks2 = k0 ^ k1 ^ 0x1BD11BDAu;
    x0 += k0; x1 += k1;
#define TF_R(r) { x0 += x1; x1 = rotl32(x1, (r)); x1 ^= x0; }
    TF_R(13) TF_R(15) TF_R(26) TF_R(6)
    x0 += k1;  x1 += ks2 + 1u;
    TF_R(17) TF_R(29) TF_R(16) TF_R(24)
    x0 += ks2; x1 += k0 + 2u;
    TF_R(13) TF_R(15) TF_R(26) TF_R(6)
    x0 += k0;  x1 += k1 + 3u;
    TF_R(17) TF_R(29) TF_R(16) TF_R(24)
    x0 += k1;  x1 += ks2 + 4u;
    TF_R(13) TF_R(15) TF_R(26) TF_R(6)
    x0 += ks2; x1 += k0 + 5u;
#undef TF_R
    o0 = x0; o1 = x1;
}

// ---------------- XLA-matching math ----------------
__device__ __forceinline__ float erfinv_xla(float x) {
    float w = -log1pf(-x * x);
    float p;
    if (w < 5.0f) {
        w = w - 2.5f;
        p = 2.81022636e-08f;
        p = fmaf(p, w, 3.43273939e-07f);
        p = fmaf(p, w, -3.5233877e-06f);
        p = fmaf(p, w, -4.39150654e-06f);
        p = fmaf(p, w, 0.00021858087f);
        p = fmaf(p, w, -0.00125372503f);
        p = fmaf(p, w, -0.00417768164f);
        p = fmaf(p, w, 0.246640727f);
        p = fmaf(p, w, 1.50140941f);
    } else {
        w = sqrtf(w) - 3.0f;
        p = -0.000200214257f;
        p = fmaf(p, w, 0.000100950558f);
        p = fmaf(p, w, 0.00134934322f);
        p = fmaf(p, w, -0.00367342844f);
        p = fmaf(p, w, 0.00573950773f);
        p = fmaf(p, w, -0.0076224613f);
        p = fmaf(p, w, 0.00943887047f);
        p = fmaf(p, w, 1.00167406f);
        p = fmaf(p, w, 2.83297682f);
    }
    return p * x;
}

__device__ __forceinline__ float tanh_xla(float x) {
    const float kMax = 7.90531110763549805f;
    float xc = fminf(fmaxf(x, -kMax), kMax);
    float x2 = xc * xc;
    float np_ = fmaf(x2, -2.76076847742355e-16f, 2.00018790482477e-13f);
    np_ = fmaf(x2, np_, -8.60467152213735e-11f);
    np_ = fmaf(x2, np_, 5.12229709037114e-08f);
    np_ = fmaf(x2, np_, 1.48572235717979e-05f);
    np_ = fmaf(x2, np_, 6.37261928875436e-04f);
    np_ = fmaf(x2, np_, 4.89352455891786e-03f);
    np_ = xc * np_;
    float dp = fmaf(x2, 1.19825839466702e-06f, 1.18534705686654e-04f);
    dp = fmaf(x2, dp, 2.26843463243900e-03f);
    dp = fmaf(x2, dp, 4.89352518554385e-03f);
    float r = np_ / dp;
    return (fabsf(x) < 0.0004f) ? x : r;
}

__device__ __forceinline__ float bits_to_u01(uint32_t bits) {
    return __uint_as_float((bits >> 9) | 0x3F800000u) - 1.0f;
}

__device__ __forceinline__ float bits_to_scaled_normal(uint32_t bits) {
    const float lo = -0.99999994039535522461f;
    float f = bits_to_u01(bits);
    float v = fmaxf(lo, fmaf(f, 2.0f, lo));
    float n = 1.41421353816986083984f * erfinv_xla(v);
    return 0.1f * n;
}

// ---------------- Phase 0: step keys + uniforms (partitionable threefry) ----------------
__global__ void keygen_kernel() {
    int t = blockIdx.x * blockDim.x + threadIdx.x;
    if (t >= NSTEPS) return;
    uint32_t a, b;
    threefry(0u, 1u, 0u, (uint32_t)t, a, b);
    uint32_t n0, n1, u0, u1;
    threefry(a, b, 0u, 0u, n0, n1);
    threefry(a, b, 0u, 1u, u0, u1);
    g_knoise[t] = make_uint2(n0, n1);
    uint32_t c, d;
    threefry(u0, u1, 0u, 0u, c, d);
    g_u[t] = bits_to_u01(c ^ d);
}

// ---------------- Phase 1: scaled normals ----------------
__global__ void noise_kernel() {
    int t = blockIdx.x;
    int i = threadIdx.x;
    uint2 k = g_knoise[t];
    uint32_t r0, r1;
    threefry(k.x, k.y, 0u, (uint32_t)i, r0, r1);
    g_sn[t * DD + i] = bits_to_scaled_normal(r0 ^ r1);
}

// ---------------- Phase 2: N = sn @ W1  (fp32 FFMA GEMM, DRAM-bound, ~3us) ----------------
#define BM 64
#define BN 64
#define BK 16
__global__ __launch_bounds__(256) void gemm_kernel(const float* __restrict__ W1) {
    __shared__ float As[BK][BM];
    __shared__ float Bs[BK][BN];
    int m0 = blockIdx.y * BM;
    int n0 = blockIdx.x * BN;
    int tid = threadIdx.x;
    int tx = tid % 16, ty = tid / 16;
    float acc[4][4] = {};
    for (int k0 = 0; k0 < DD; k0 += BK) {
#pragma unroll
        for (int l = tid; l < BM * BK; l += 256) {
            int m = l / BK, k = l % BK;
            As[k][m] = g_sn[(m0 + m) * DD + k0 + k];
        }
#pragma unroll
        for (int l = tid; l < BK * BN; l += 256) {
            int k = l / BN, n = l % BN;
            Bs[k][n] = W1[(k0 + k) * HH + n0 + n];
        }
        __syncthreads();
#pragma unroll
        for (int kk = 0; kk < BK; kk++) {
            float a[4], b[4];
#pragma unroll
            for (int i = 0; i < 4; i++) a[i] = As[kk][ty * 4 + i];
#pragma unroll
            for (int j = 0; j < 4; j++) b[j] = Bs[kk][tx * 4 + j];
#pragma unroll
            for (int i = 0; i < 4; i++)
#pragma unroll
                for (int j = 0; j < 4; j++)
                    acc[i][j] = fmaf(a[i], b[j], acc[i][j]);
        }
        __syncthreads();
    }
#pragma unroll
    for (int i = 0; i < 4; i++)
#pragma unroll
        for (int j = 0; j < 4; j++)
            g_N[(m0 + ty * 4 + i) * HH + n0 + tx * 4 + j] = acc[i][j];
}

// ---------------- Phase 3: sequential MH chain ----------------
// 128 threads (4 warps, 1/SMSP), 8 hidden units/thread, 4 x-dims/thread.
// Single barrier per step, double-buffered 4-way partials, decision via
// multiply-compare (u*(p_old+eps) < p_new) — no division on the critical path.
__global__ __launch_bounds__(128, 1) void chain_kernel(
    const float* __restrict__ x0, const float* __restrict__ W1,
    const float* __restrict__ b1, const float* __restrict__ W2,
    const float* __restrict__ b2, float* __restrict__ out) {
    int tid  = threadIdx.x;
    int lane = tid & 31;
    int w    = tid >> 5;

    __shared__ __align__(16) float s_part[2][4];
    __shared__ float s_x0[DD];
    __shared__ float s_u[NSTEPS];

    for (int i = tid; i < NSTEPS; i += 128) s_u[i] = g_u[i];
    {
        float4 t4 = ((const float4*)x0)[tid];
        s_x0[4 * tid]     = t4.x; s_x0[4 * tid + 1] = t4.y;
        s_x0[4 * tid + 2] = t4.z; s_x0[4 * tid + 3] = t4.w;
    }
    __syncthreads();

    // z_j = b1_j + x0 @ W1[:, j]   (units 8*tid .. 8*tid+7)
    float z[8];
    {
        float4 b0 = ((const float4*)b1)[2 * tid];
        float4 b1v = ((const float4*)b1)[2 * tid + 1];
        z[0] = b0.x;  z[1] = b0.y;  z[2] = b0.z;  z[3] = b0.w;
        z[4] = b1v.x; z[5] = b1v.y; z[6] = b1v.z; z[7] = b1v.w;
    }
    const float4* W1v = (const float4*)W1;
#pragma unroll 4
    for (int d = 0; d < DD; d++) {
        float xv = s_x0[d];
        float4 wa = W1v[d * (HH / 4) + 2 * tid];
        float4 wb = W1v[d * (HH / 4) + 2 * tid + 1];
        z[0] = fmaf(xv, wa.x, z[0]); z[1] = fmaf(xv, wa.y, z[1]);
        z[2] = fmaf(xv, wa.z, z[2]); z[3] = fmaf(xv, wa.w, z[3]);
        z[4] = fmaf(xv, wb.x, z[4]); z[5] = fmaf(xv, wb.y, z[5]);
        z[6] = fmaf(xv, wb.z, z[6]); z[7] = fmaf(xv, wb.w, z[7]);
    }

    float w2[8];
    {
        float4 a = ((const float4*)W2)[2 * tid];
        float4 b = ((const float4*)W2)[2 * tid + 1];
        w2[0] = a.x; w2[1] = a.y; w2[2] = a.z; w2[3] = a.w;
        w2[4] = b.x; w2[5] = b.y; w2[6] = b.z; w2[7] = b.w;
    }
    float b2v = b2[0];
    float4 x = ((const float4*)x0)[tid];

    const float4* Nv  = (const float4*)g_N;   // row stride HH/4 = 256
    const float4* snv = (const float4*)g_sn;  // row stride DD/4 = 128

    // p_old = psi2(x0), same reduction structure as the loop (buffer 1)
    float p_old;
    {
        float pa = tanh_xla(z[0]) * w2[0];
        float pb = tanh_xla(z[1]) * w2[1];
        pa = fmaf(tanh_xla(z[2]), w2[2], pa);
        pb = fmaf(tanh_xla(z[3]), w2[3], pb);
        pa = fmaf(tanh_xla(z[4]), w2[4], pa);
        pb = fmaf(tanh_xla(z[5]), w2[5], pb);
        pa = fmaf(tanh_xla(z[6]), w2[6], pa);
        pb = fmaf(tanh_xla(z[7]), w2[7], pb);
        float p = pa + pb;
#pragma unroll
        for (int o = 16; o; o >>= 1) p += __shfl_xor_sync(0xFFFFFFFFu, p, o);
        if (lane == 0) s_part[1][w] = p;
        __syncthreads();
        float4 q = *(const float4*)&s_part[1][0];
        float v = (q.x + q.y) + (q.z + q.w);
        float o_ = v + b2v;
        p_old = o_ * o_;
    }

    // prefetch rows 0 and 1 (decision-independent; L2-resident)
    float Nc[8], Nn[8];
    {
        float4 a = Nv[2 * tid], b = Nv[2 * tid + 1];
        Nc[0] = a.x; Nc[1] = a.y; Nc[2] = a.z; Nc[3] = a.w;
        Nc[4] = b.x; Nc[5] = b.y; Nc[6] = b.z; Nc[7] = b.w;
        a = Nv[256 + 2 * tid]; b = Nv[256 + 2 * tid + 1];
        Nn[0] = a.x; Nn[1] = a.y; Nn[2] = a.z; Nn[3] = a.w;
        Nn[4] = b.x; Nn[5] = b.y; Nn[6] = b.z; Nn[7] = b.w;
    }
    float4 sc  = snv[tid];
    float4 snn = snv[128 + tid];
    float  uc  = s_u[0];
    float  un  = s_u[1];

    for (int t = 0; t < NSTEPS; t++) {
        float pre[8];
#pragma unroll
        for (int i = 0; i < 8; i++) pre[i] = z[i] + Nc[i];

        // two accumulation chains (halved dependent-FMA depth), 8-wide tanh ILP
        float pa = tanh_xla(pre[0]) * w2[0];
        float pb = tanh_xla(pre[1]) * w2[1];
        pa = fmaf(tanh_xla(pre[2]), w2[2], pa);
        pb = fmaf(tanh_xla(pre[3]), w2[3], pb);
        pa = fmaf(tanh_xla(pre[4]), w2[4], pa);
        pb = fmaf(tanh_xla(pre[5]), w2[5], pb);
        pa = fmaf(tanh_xla(pre[6]), w2[6], pa);
        pb = fmaf(tanh_xla(pre[7]), w2[7], pb);
        float p = pa + pb;
#pragma unroll
        for (int o = 16; o; o >>= 1) p += __shfl_xor_sync(0xFFFFFFFFu, p, o);
        int buf = t & 1;
        if (lane == 0) s_part[buf][w] = p;
        __syncthreads();                       // the only barrier per step

        float4 q = *(const float4*)&s_part[buf][0];
        float v = (q.x + q.y) + (q.z + q.w);
        float o_    = v + b2v;
        float p_new = o_ * o_;
        // accept iff u < min(p_new/(p_old+eps), 1); with u in [0,1) this is
        // exactly u*(p_old+eps) < p_new (rounding-tie risk ~1e-7/step)
        bool acc = (uc * (p_old + 1e-12f) < p_new);
        if (acc) {
            p_old = p_new;
#pragma unroll
            for (int i = 0; i < 8; i++) z[i] = pre[i];
            x.x += sc.x; x.y += sc.y; x.z += sc.z; x.w += sc.w;
        }
        if (t >= BURN) ((float4*)out)[(t - BURN) * (DD / 4) + tid] = x;

        // rotate / prefetch depth 2 (clamped index; stale values feed no decision)
#pragma unroll
        for (int i = 0; i < 8; i++) Nc[i] = Nn[i];
        sc = snn; uc = un;
        int tn = t + 2 < NSTEPS ? t + 2 : NSTEPS - 1;
        {
            float4 a = Nv[tn * 256 + 2 * tid], b = Nv[tn * 256 + 2 * tid + 1];
            Nn[0] = a.x; Nn[1] = a.y; Nn[2] = a.z; Nn[3] = a.w;
            Nn[4] = b.x; Nn[5] = b.y; Nn[6] = b.z; Nn[7] = b.w;
        }
        snn = snv[tn * 128 + tid];
        un  = s_u[tn];
    }
}

// ---------------- launch ----------------
extern "C" void kernel_launch(void* const* d_in, const int* in_sizes, int n_in,
                              void* d_out, int out_size) {
    const float* x0 = (const float*)d_in[0];
    const float* W1 = (const float*)d_in[1];
    const float* b1 = (const float*)d_in[2];
    const float* W2 = (const float*)d_in[3];
    const float* b2 = (const float*)d_in[4];
    float* out = (float*)d_out;

    keygen_kernel<<<(NSTEPS + 255) / 256, 256>>>();
    noise_kernel<<<NSTEPS, 512>>>();
    gemm_kernel<<<dim3(HH / BN, NSTEPS / BM), 256>>>(W1);
    chain_kernel<<<1, 128>>>(x0, W1, b1, W2, b2, out);
}

// round 9
// speedup vs baseline: 1.4982x; 1.2783x over previous
#include <cuda_runtime.h>
#include <stdint.h>

#define NSTEPS 2176
#define BURN   128
#define DD     512
#define HH     1024

// Scratch (static device globals — no allocation anywhere)
__device__ float g_sn[NSTEPS * DD];   // 0.1 * normal noise rows
__device__ float g_N [NSTEPS * HH];   // (0.1*noise_t) @ W1
__device__ float g_u [NSTEPS];        // uniform accept draws
__device__ uint2 g_knoise[NSTEPS];    // per-step noise subkeys

// ---------------- threefry2x32 (exact JAX) ----------------
__device__ __forceinline__ uint32_t rotl32(uint32_t v, int r) {
    return (v << r) | (v >> (32 - r));
}

__device__ __forceinline__ void threefry(uint32_t k0, uint32_t k1,
                                         uint32_t x0, uint32_t x1,
                                         uint32_t& o0, uint32_t& o1) {
    uint32_t ks2 = k0 ^ k1 ^ 0x1BD11BDAu;
    x0 += k0; x1 += k1;
#define TF_R(r) { x0 += x1; x1 = rotl32(x1, (r)); x1 ^= x0; }
    TF_R(13) TF_R(15) TF_R(26) TF_R(6)
    x0 += k1;  x1 += ks2 + 1u;
    TF_R(17) TF_R(29) TF_R(16) TF_R(24)
    x0 += ks2; x1 += k0 + 2u;
    TF_R(13) TF_R(15) TF_R(26) TF_R(6)
    x0 += k0;  x1 += k1 + 3u;
    TF_R(17) TF_R(29) TF_R(16) TF_R(24)
    x0 += k1;  x1 += ks2 + 4u;
    TF_R(13) TF_R(15) TF_R(26) TF_R(6)
    x0 += ks2; x1 += k0 + 5u;
#undef TF_R
    o0 = x0; o1 = x1;
}

// ---------------- XLA-matching math ----------------
__device__ __forceinline__ float erfinv_xla(float x) {
    float w = -log1pf(-x * x);
    float p;
    if (w < 5.0f) {
        w = w - 2.5f;
        p = 2.81022636e-08f;
        p = fmaf(p, w, 3.43273939e-07f);
        p = fmaf(p, w, -3.5233877e-06f);
        p = fmaf(p, w, -4.39150654e-06f);
        p = fmaf(p, w, 0.00021858087f);
        p = fmaf(p, w, -0.00125372503f);
        p = fmaf(p, w, -0.00417768164f);
        p = fmaf(p, w, 0.246640727f);
        p = fmaf(p, w, 1.50140941f);
    } else {
        w = sqrtf(w) - 3.0f;
        p = -0.000200214257f;
        p = fmaf(p, w, 0.000100950558f);
        p = fmaf(p, w, 0.00134934322f);
        p = fmaf(p, w, -0.00367342844f);
        p = fmaf(p, w, 0.00573950773f);
        p = fmaf(p, w, -0.0076224613f);
        p = fmaf(p, w, 0.00943887047f);
        p = fmaf(p, w, 1.00167406f);
        p = fmaf(p, w, 2.83297682f);
    }
    return p * x;
}

__device__ __forceinline__ float tanh_xla(float x) {
    const float kMax = 7.90531110763549805f;
    float xc = fminf(fmaxf(x, -kMax), kMax);
    float x2 = xc * xc;
    float np_ = fmaf(x2, -2.76076847742355e-16f, 2.00018790482477e-13f);
    np_ = fmaf(x2, np_, -8.60467152213735e-11f);
    np_ = fmaf(x2, np_, 5.12229709037114e-08f);
    np_ = fmaf(x2, np_, 1.48572235717979e-05f);
    np_ = fmaf(x2, np_, 6.37261928875436e-04f);
    np_ = fmaf(x2, np_, 4.89352455891786e-03f);
    np_ = xc * np_;
    float dp = fmaf(x2, 1.19825839466702e-06f, 1.18534705686654e-04f);
    dp = fmaf(x2, dp, 2.26843463243900e-03f);
    dp = fmaf(x2, dp, 4.89352518554385e-03f);
    float r = np_ / dp;
    return (fabsf(x) < 0.0004f) ? x : r;
}

__device__ __forceinline__ float bits_to_u01(uint32_t bits) {
    return __uint_as_float((bits >> 9) | 0x3F800000u) - 1.0f;
}

__device__ __forceinline__ float bits_to_scaled_normal(uint32_t bits) {
    const float lo = -0.99999994039535522461f;
    float f = bits_to_u01(bits);
    float v = fmaxf(lo, fmaf(f, 2.0f, lo));
    float n = 1.41421353816986083984f * erfinv_xla(v);
    return 0.1f * n;
}

// ---------------- Phase 0: step keys + uniforms (partitionable threefry) ----------------
__global__ void keygen_kernel() {
    int t = blockIdx.x * blockDim.x + threadIdx.x;
    if (t >= NSTEPS) return;
    uint32_t a, b;
    threefry(0u, 1u, 0u, (uint32_t)t, a, b);
    uint32_t n0, n1, u0, u1;
    threefry(a, b, 0u, 0u, n0, n1);
    threefry(a, b, 0u, 1u, u0, u1);
    g_knoise[t] = make_uint2(n0, n1);
    uint32_t c, d;
    threefry(u0, u1, 0u, 0u, c, d);
    g_u[t] = bits_to_u01(c ^ d);
}

// ---------------- Phase 1: scaled normals ----------------
__global__ void noise_kernel() {
    int t = blockIdx.x;
    int i = threadIdx.x;
    uint2 k = g_knoise[t];
    uint32_t r0, r1;
    threefry(k.x, k.y, 0u, (uint32_t)i, r0, r1);
    g_sn[t * DD + i] = bits_to_scaled_normal(r0 ^ r1);
}

// ---------------- Phase 2: N = sn @ W1  (fp32 FFMA GEMM, DRAM-bound, ~3us) ----------------
#define BM 64
#define BN 64
#define BK 16
__global__ __launch_bounds__(256) void gemm_kernel(const float* __restrict__ W1) {
    __shared__ float As[BK][BM];
    __shared__ float Bs[BK][BN];
    int m0 = blockIdx.y * BM;
    int n0 = blockIdx.x * BN;
    int tid = threadIdx.x;
    int tx = tid % 16, ty = tid / 16;
    float acc[4][4] = {};
    for (int k0 = 0; k0 < DD; k0 += BK) {
#pragma unroll
        for (int l = tid; l < BM * BK; l += 256) {
            int m = l / BK, k = l % BK;
            As[k][m] = g_sn[(m0 + m) * DD + k0 + k];
        }
#pragma unroll
        for (int l = tid; l < BK * BN; l += 256) {
            int k = l / BN, n = l % BN;
            Bs[k][n] = W1[(k0 + k) * HH + n0 + n];
        }
        __syncthreads();
#pragma unroll
        for (int kk = 0; kk < BK; kk++) {
            float a[4], b[4];
#pragma unroll
            for (int i = 0; i < 4; i++) a[i] = As[kk][ty * 4 + i];
#pragma unroll
            for (int j = 0; j < 4; j++) b[j] = Bs[kk][tx * 4 + j];
#pragma unroll
            for (int i = 0; i < 4; i++)
#pragma unroll
                for (int j = 0; j < 4; j++)
                    acc[i][j] = fmaf(a[i], b[j], acc[i][j]);
        }
        __syncthreads();
    }
#pragma unroll
    for (int i = 0; i < 4; i++)
#pragma unroll
        for (int j = 0; j < 4; j++)
            g_N[(m0 + ty * 4 + i) * HH + n0 + tx * 4 + j] = acc[i][j];
}

// ---------------- Phase 3: sequential MH chain ----------------
// 512 threads (16 warps, 4/SMSP) — warp overlap is the latency-hiding resource.
// 2 hidden units/thread, 1 x-dim/thread. Single barrier per step,
// double-buffered 16-way partials, multiply-compare accept (no division).
__global__ __launch_bounds__(512, 1) void chain_kernel(
    const float* __restrict__ x0, const float* __restrict__ W1,
    const float* __restrict__ b1, const float* __restrict__ W2,
    const float* __restrict__ b2, float* __restrict__ out) {
    int tid  = threadIdx.x;
    int lane = tid & 31;
    int w    = tid >> 5;

    __shared__ __align__(16) float s_part[2][16];
    __shared__ float s_x0[DD];
    __shared__ float s_u[NSTEPS];

    for (int i = tid; i < NSTEPS; i += 512) s_u[i] = g_u[i];
    if (tid < DD) s_x0[tid] = x0[tid];
    __syncthreads();

    // z_j = b1_j + x0 @ W1[:, j]   (units 2*tid, 2*tid+1)
    float z0, z1;
    {
        float2 bv = ((const float2*)b1)[tid];
        z0 = bv.x; z1 = bv.y;
    }
    const float2* W1v = (const float2*)W1;
#pragma unroll 8
    for (int d = 0; d < DD; d++) {
        float xv = s_x0[d];
        float2 wv = W1v[d * (HH / 2) + tid];
        z0 = fmaf(xv, wv.x, z0);
        z1 = fmaf(xv, wv.y, z1);
    }

    float2 w2v = ((const float2*)W2)[tid];
    float b2v = b2[0];
    float xj = x0[tid];

    const float2* Nv  = (const float2*)g_N;   // row stride HH/2 = 512
    const float*  snv = g_sn;                 // row stride DD = 512

    // p_old = psi2(x0), same reduction structure as the loop (buffer 1)
    float p_old;
    {
        float p = tanh_xla(z0) * w2v.x;
        p = fmaf(tanh_xla(z1), w2v.y, p);
#pragma unroll
        for (int o = 16; o; o >>= 1) p += __shfl_xor_sync(0xFFFFFFFFu, p, o);
        if (lane == 0) s_part[1][w] = p;
        __syncthreads();
        float4 q0 = *(const float4*)&s_part[1][0];
        float4 q1 = *(const float4*)&s_part[1][4];
        float4 q2 = *(const float4*)&s_part[1][8];
        float4 q3 = *(const float4*)&s_part[1][12];
        float v = (((q0.x + q0.y) + (q0.z + q0.w)) + ((q1.x + q1.y) + (q1.z + q1.w)))
                + (((q2.x + q2.y) + (q2.z + q2.w)) + ((q3.x + q3.y) + (q3.z + q3.w)));
        float o_ = v + b2v;
        p_old = o_ * o_;
    }

    // prefetch rows 0 and 1 (decision-independent; L2-resident)
    float2 Nc  = Nv[tid];
    float2 Nn  = Nv[512 + tid];
    float  sc  = snv[tid];
    float  snn = snv[DD + tid];
    float  uc  = s_u[0];
    float  un  = s_u[1];

    for (int t = 0; t < NSTEPS; t++) {
        float pre0 = z0 + Nc.x;
        float pre1 = z1 + Nc.y;
        float p = tanh_xla(pre0) * w2v.x;
        p = fmaf(tanh_xla(pre1), w2v.y, p);
#pragma unroll
        for (int o = 16; o; o >>= 1) p += __shfl_xor_sync(0xFFFFFFFFu, p, o);
        int buf = t & 1;
        if (lane == 0) s_part[buf][w] = p;
        __syncthreads();                       // the only barrier per step

        float4 q0 = *(const float4*)&s_part[buf][0];
        float4 q1 = *(const float4*)&s_part[buf][4];
        float4 q2 = *(const float4*)&s_part[buf][8];
        float4 q3 = *(const float4*)&s_part[buf][12];
        float v = (((q0.x + q0.y) + (q0.z + q0.w)) + ((q1.x + q1.y) + (q1.z + q1.w)))
                + (((q2.x + q2.y) + (q2.z + q2.w)) + ((q3.x + q3.y) + (q3.z + q3.w)));
        float o_    = v + b2v;
        float p_new = o_ * o_;
        // accept iff u < min(p_new/(p_old+eps), 1); u in [0,1) makes this
        // exactly u*(p_old+eps) < p_new (validated bit-identical in R7)
        bool acc = (uc * (p_old + 1e-12f) < p_new);
        if (acc) {
            p_old = p_new;
            z0 = pre0; z1 = pre1;
            xj += sc;
        }
        if (t >= BURN) out[(t - BURN) * DD + tid] = xj;

        // rotate / prefetch depth 2 (clamped; stale values feed no decision)
        Nc = Nn; sc = snn; uc = un;
        int tn = t + 2 < NSTEPS ? t + 2 : NSTEPS - 1;
        Nn  = Nv[tn * 512 + tid];
        snn = snv[tn * DD + tid];
        un  = s_u[tn];
    }
}

// ---------------- launch ----------------
extern "C" void kernel_launch(void* const* d_in, const int* in_sizes, int n_in,
                              void* d_out, int out_size) {
    const float* x0 = (const float*)d_in[0];
    const float* W1 = (const float*)d_in[1];
    const float* b1 = (const float*)d_in[2];
    const float* W2 = (const float*)d_in[3];
    const float* b2 = (const float*)d_in[4];
    float* out = (float*)d_out;

    keygen_kernel<<<(NSTEPS + 255) / 256, 256>>>();
    noise_kernel<<<NSTEPS, 512>>>();
    gemm_kernel<<<dim3(HH / BN, NSTEPS / BM), 256>>>(W1);
    chain_kernel<<<1, 512>>>(x0, W1, b1, W2, b2, out);
}

// round 12
// speedup vs baseline: 1.7129x; 1.1433x over previous
#include <cuda_runtime.h>
#include <stdint.h>

#define NSTEPS 2176
#define BURN   128
#define DD     512
#define HH     1024

// Scratch (static device globals — no allocation anywhere)
__device__ float g_sn[NSTEPS * DD];   // 0.1 * normal noise rows
__device__ float g_N [NSTEPS * HH];   // (0.1*noise_t) @ W1
__device__ float g_u [NSTEPS];        // uniform accept draws
__device__ uint2 g_knoise[NSTEPS];    // per-step noise subkeys

// ---------------- threefry2x32 (exact JAX) ----------------
__device__ __forceinline__ uint32_t rotl32(uint32_t v, int r) {
    return (v << r) | (v >> (32 - r));
}

__device__ __forceinline__ void threefry(uint32_t k0, uint32_t k1,
                                         uint32_t x0, uint32_t x1,
                                         uint32_t& o0, uint32_t& o1) {
    uint32_t ks2 = k0 ^ k1 ^ 0x1BD11BDAu;
    x0 += k0; x1 += k1;
#define TF_R(r) { x0 += x1; x1 = rotl32(x1, (r)); x1 ^= x0; }
    TF_R(13) TF_R(15) TF_R(26) TF_R(6)
    x0 += k1;  x1 += ks2 + 1u;
    TF_R(17) TF_R(29) TF_R(16) TF_R(24)
    x0 += ks2; x1 += k0 + 2u;
    TF_R(13) TF_R(15) TF_R(26) TF_R(6)
    x0 += k0;  x1 += k1 + 3u;
    TF_R(17) TF_R(29) TF_R(16) TF_R(24)
    x0 += k1;  x1 += ks2 + 4u;
    TF_R(13) TF_R(15) TF_R(26) TF_R(6)
    x0 += ks2; x1 += k0 + 5u;
#undef TF_R
    o0 = x0; o1 = x1;
}

// ---------------- XLA-matching math (exact paths for RNG: unchanged) ----------------
__device__ __forceinline__ float erfinv_xla(float x) {
    float w = -log1pf(-x * x);
    float p;
    if (w < 5.0f) {
        w = w - 2.5f;
        p = 2.81022636e-08f;
        p = fmaf(p, w, 3.43273939e-07f);
        p = fmaf(p, w, -3.5233877e-06f);
        p = fmaf(p, w, -4.39150654e-06f);
        p = fmaf(p, w, 0.00021858087f);
        p = fmaf(p, w, -0.00125372503f);
        p = fmaf(p, w, -0.00417768164f);
        p = fmaf(p, w, 0.246640727f);
        p = fmaf(p, w, 1.50140941f);
    } else {
        w = sqrtf(w) - 3.0f;
        p = -0.000200214257f;
        p = fmaf(p, w, 0.000100950558f);
        p = fmaf(p, w, 0.00134934322f);
        p = fmaf(p, w, -0.00367342844f);
        p = fmaf(p, w, 0.00573950773f);
        p = fmaf(p, w, -0.0076224613f);
        p = fmaf(p, w, 0.00943887047f);
        p = fmaf(p, w, 1.00167406f);
        p = fmaf(p, w, 2.83297682f);
    }
    return p * x;
}

// XLA tanh polynomial with approx division (MUFU.RCP+MUL, rel err <= 3.6e-7).
// Outputs are exact sums of sn rows selected by decisions, so absent a
// decision flip the trajectory is bit-identical (oracle: rel_err 2.883114e-07).
__device__ __forceinline__ float tanh_fast(float x) {
    const float kMax = 7.90531110763549805f;
    float xc = fminf(fmaxf(x, -kMax), kMax);
    float x2 = xc * xc;
    float np_ = fmaf(x2, -2.76076847742355e-16f, 2.00018790482477e-13f);
    np_ = fmaf(x2, np_, -8.60467152213735e-11f);
    np_ = fmaf(x2, np_, 5.12229709037114e-08f);
    np_ = fmaf(x2, np_, 1.48572235717979e-05f);
    np_ = fmaf(x2, np_, 6.37261928875436e-04f);
    np_ = fmaf(x2, np_, 4.89352455891786e-03f);
    np_ = xc * np_;
    float dp = fmaf(x2, 1.19825839466702e-06f, 1.18534705686654e-04f);
    dp = fmaf(x2, dp, 2.26843463243900e-03f);
    dp = fmaf(x2, dp, 4.89352518554385e-03f);
    float r = __fdividef(np_, dp);     // div.approx.f32
    return (fabsf(x) < 0.0004f) ? x : r;
}

__device__ __forceinline__ float bits_to_u01(uint32_t bits) {
    return __uint_as_float((bits >> 9) | 0x3F800000u) - 1.0f;
}

__device__ __forceinline__ float bits_to_scaled_normal(uint32_t bits) {
    const float lo = -0.99999994039535522461f;
    float f = bits_to_u01(bits);
    float v = fmaxf(lo, fmaf(f, 2.0f, lo));
    float n = 1.41421353816986083984f * erfinv_xla(v);
    return 0.1f * n;
}

// ---------------- Phase 0: step keys + uniforms (partitionable threefry) ----------------
__global__ void keygen_kernel() {
    int t = blockIdx.x * blockDim.x + threadIdx.x;
    if (t >= NSTEPS) return;
    uint32_t a, b;
    threefry(0u, 1u, 0u, (uint32_t)t, a, b);
    uint32_t n0, n1, u0, u1;
    threefry(a, b, 0u, 0u, n0, n1);
    threefry(a, b, 0u, 1u, u0, u1);
    g_knoise[t] = make_uint2(n0, n1);
    uint32_t c, d;
    threefry(u0, u1, 0u, 0u, c, d);
    g_u[t] = bits_to_u01(c ^ d);
}

// ---------------- Phase 1: scaled normals ----------------
__global__ void noise_kernel() {
    int t = blockIdx.x;
    int i = threadIdx.x;
    uint2 k = g_knoise[t];
    uint32_t r0, r1;
    threefry(k.x, k.y, 0u, (uint32_t)i, r0, r1);
    g_sn[t * DD + i] = bits_to_scaled_normal(r0 ^ r1);
}

// ---------------- Phase 2: N = sn @ W1  (fp32 FFMA GEMM, DRAM-bound, ~3us) ----------------
#define BM 64
#define BN 64
#define BK 16
__global__ __launch_bounds__(256) void gemm_kernel(const float* __restrict__ W1) {
    __shared__ float As[BK][BM];
    __shared__ float Bs[BK][BN];
    int m0 = blockIdx.y * BM;
    int n0 = blockIdx.x * BN;
    int tid = threadIdx.x;
    int tx = tid % 16, ty = tid / 16;
    float acc[4][4] = {};
    for (int k0 = 0; k0 < DD; k0 += BK) {
#pragma unroll
        for (int l = tid; l < BM * BK; l += 256) {
            int m = l / BK, k = l % BK;
            As[k][m] = g_sn[(m0 + m) * DD + k0 + k];
        }
#pragma unroll
        for (int l = tid; l < BK * BN; l += 256) {
            int k = l / BN, n = l % BN;
            Bs[k][n] = W1[(k0 + k) * HH + n0 + n];
        }
        __syncthreads();
#pragma unroll
        for (int kk = 0; kk < BK; kk++) {
            float a[4], b[4];
#pragma unroll
            for (int i = 0; i < 4; i++) a[i] = As[kk][ty * 4 + i];
#pragma unroll
            for (int j = 0; j < 4; j++) b[j] = Bs[kk][tx * 4 + j];
#pragma unroll
            for (int i = 0; i < 4; i++)
#pragma unroll
                for (int j = 0; j < 4; j++)
                    acc[i][j] = fmaf(a[i], b[j], acc[i][j]);
        }
        __syncthreads();
    }
#pragma unroll
    for (int i = 0; i < 4; i++)
#pragma unroll
        for (int j = 0; j < 4; j++)
            g_N[(m0 + ty * 4 + i) * HH + n0 + tx * 4 + j] = acc[i][j];
}

// ---------------- Phase 3: sequential MH chain ----------------
// 256 threads (8 warps), 4 hidden units/thread, 2 x-dims/thread.
// Single barrier/step, double-buffered 8-way partials, shfl butterfly warp sum,
// approx-division tanh, multiply-compare accept (no IEEE division anywhere).
__global__ __launch_bounds__(256, 1) void chain_kernel(
    const float* __restrict__ x0, const float* __restrict__ W1,
    const float* __restrict__ b1, const float* __restrict__ W2,
    const float* __restrict__ b2, float* __restrict__ out) {
    int tid  = threadIdx.x;
    int lane = tid & 31;
    int w    = tid >> 5;

    __shared__ __align__(16) float s_part[2][8];
    __shared__ float s_x0[DD];
    __shared__ float s_u[NSTEPS];

    for (int i = tid; i < NSTEPS; i += 256) s_u[i] = g_u[i];
    {
        float2 t2 = ((const float2*)x0)[tid];
        s_x0[2 * tid] = t2.x; s_x0[2 * tid + 1] = t2.y;
    }
    __syncthreads();

    // z_j = b1_j + x0 @ W1[:, j]
    float z[4];
    {
        float4 bv = ((const float4*)b1)[tid];
        z[0] = bv.x; z[1] = bv.y; z[2] = bv.z; z[3] = bv.w;
    }
    const float4* W1v = (const float4*)W1;
#pragma unroll 4
    for (int d = 0; d < DD; d++) {
        float xv = s_x0[d];
        float4 wv = W1v[d * (HH / 4) + tid];
        z[0] = fmaf(xv, wv.x, z[0]);
        z[1] = fmaf(xv, wv.y, z[1]);
        z[2] = fmaf(xv, wv.z, z[2]);
        z[3] = fmaf(xv, wv.w, z[3]);
    }

    float4 w2v = ((const float4*)W2)[tid];
    float b2v = b2[0];
    float2 x = ((const float2*)x0)[tid];

    const float4* Nv  = (const float4*)g_N;   // row stride HH/4 = 256
    const float2* snv = (const float2*)g_sn;  // row stride DD/2 = 256

    // p_old = psi2(x0), same reduction structure as the loop (buffer 1)
    float p_old;
    {
        float h, p;
        h = tanh_fast(z[0]); p = h * w2v.x;
        h = tanh_fast(z[1]); p = fmaf(h, w2v.y, p);
        h = tanh_fast(z[2]); p = fmaf(h, w2v.z, p);
        h = tanh_fast(z[3]); p = fmaf(h, w2v.w, p);
#pragma unroll
        for (int o = 16; o; o >>= 1) p += __shfl_xor_sync(0xFFFFFFFFu, p, o);
        if (lane == 0) s_part[1][w] = p;
        __syncthreads();
        float4 qa = *(const float4*)&s_part[1][0];
        float4 qb = *(const float4*)&s_part[1][4];
        float v = ((qa.x + qa.y) + (qa.z + qa.w)) + ((qb.x + qb.y) + (qb.z + qb.w));
        float o_ = v + b2v;
        p_old = o_ * o_;
    }

    // prefetch rows 0 and 1 (decision-independent; L2-resident)
    float4 Nc  = Nv[tid];
    float4 Nn  = Nv[256 + tid];
    float2 sc  = snv[tid];
    float2 snn = snv[256 + tid];
    float  uc  = s_u[0];
    float  un  = s_u[1];

    for (int t = 0; t < NSTEPS; t++) {
        float pre0 = z[0] + Nc.x;
        float pre1 = z[1] + Nc.y;
        float pre2 = z[2] + Nc.z;
        float pre3 = z[3] + Nc.w;
        float h, p;
        h = tanh_fast(pre0); p = h * w2v.x;
        h = tanh_fast(pre1); p = fmaf(h, w2v.y, p);
        h = tanh_fast(pre2); p = fmaf(h, w2v.z, p);
        h = tanh_fast(pre3); p = fmaf(h, w2v.w, p);
#pragma unroll
        for (int o = 16; o; o >>= 1) p += __shfl_xor_sync(0xFFFFFFFFu, p, o);
        int buf = t & 1;
        if (lane == 0) s_part[buf][w] = p;
        __syncthreads();                        // the only barrier per step

        float4 qa = *(const float4*)&s_part[buf][0];
        float4 qb = *(const float4*)&s_part[buf][4];
        float v = ((qa.x + qa.y) + (qa.z + qa.w)) + ((qb.x + qb.y) + (qb.z + qb.w));
        float o_    = v + b2v;
        float p_new = o_ * o_;
        // accept iff u < min(p_new/(p_old+eps), 1); u in [0,1) makes this
        // exactly u*(p_old+eps) < p_new (validated bit-identical since R7)
        bool acc = (uc * (p_old + 1e-12f) < p_new);
        if (acc) {
            p_old = p_new;
            z[0] = pre0; z[1] = pre1; z[2] = pre2; z[3] = pre3;
            x.x += sc.x; x.y += sc.y;
        }
        if (t >= BURN) ((float2*)out)[(t - BURN) * (DD / 2) + tid] = x;

        // rotate / prefetch depth 2 (clamped; stale values feed no decision)
        Nc = Nn; sc = snn; uc = un;
        int tn = t + 2 < NSTEPS ? t + 2 : NSTEPS - 1;
        Nn  = Nv[tn * 256 + tid];
        snn = snv[tn * 256 + tid];
        un  = s_u[tn];
    }
}

// ---------------- launch ----------------
extern "C" void kernel_launch(void* const* d_in, const int* in_sizes, int n_in,
                              void* d_out, int out_size) {
    const float* x0 = (const float*)d_in[0];
    const float* W1 = (const float*)d_in[1];
    const float* b1 = (const float*)d_in[2];
    const float* W2 = (const float*)d_in[3];
    const float* b2 = (const float*)d_in[4];
    float* out = (float*)d_out;

    keygen_kernel<<<(NSTEPS + 255) / 256, 256>>>();
    noise_kernel<<<NSTEPS, 512>>>();
    gemm_kernel<<<dim3(HH / BN, NSTEPS / BM), 256>>>(W1);
    chain_kernel<<<1, 256>>>(x0, W1, b1, W2, b2, out);
}